// round 16
// baseline (speedup 1.0000x reference)
#include <cuda_runtime.h>
#include <cuda_fp16.h>
#include <math.h>
#include <stdint.h>

#define B_  16
#define D_  512
#define T_  2048
#define K_  8
#define C_  1024
#define CH_ 64
#define NQ  (B_*D_*T_)
#define TT  128
#define NBLK 2048
#define EPS 1e-2f
#define RSH 72                  // padded half row stride

// smem byte offsets
#define ABH   0                 // A: 128 x 72 halfs = 18432 B
#define BBUF  18432             // 2 bufs x 18432
#define BCN   55296             // float[1024]
#define BXN   59392             // float[128]
#define BWIN  59904             // int[128]
#define BLIST 60416             // int[128]
#define BCNT  60928             // int (pad 16)
#define BRED  60944             // float[256]
#define BXROW 61968             // float[8*64]
#define SMEM_BYTES 64016

// ---------------- scratch ----------------------------------------------------
__device__ int    g_counts[K_*C_];
__device__ float  g_cnorm[K_*C_];
__device__ float  g_cbT[K_*CH_*C_];     // exact, [k][ch][c] (rescue path)
__device__ __half g_cbHh[K_*C_*CH_];    // fp16, [k][c][ch]
__device__ float  g_loss_partial[NBLK];

// ---------------- helpers ----------------------------------------------------
__device__ __forceinline__ float fadd_rn(float a, float b) {
    float r; asm("add.f32 %0, %1, %2;" : "=f"(r) : "f"(a), "f"(b)); return r;
}
__device__ __forceinline__ void cp16(void* smem_dst, const void* gmem_src) {
    unsigned s = (unsigned)__cvta_generic_to_shared(smem_dst);
    asm volatile("cp.async.cg.shared.global [%0], [%1], 16;" :: "r"(s), "l"(gmem_src) : "memory");
}
#define CP_COMMIT() asm volatile("cp.async.commit_group;" ::: "memory")
#define CP_WAIT0()  asm volatile("cp.async.wait_group 0;" ::: "memory")
#define CP_WAIT1()  asm volatile("cp.async.wait_group 1;" ::: "memory")

#define MMA_F16(d, a0,a1,a2,a3, b0,b1) \
    asm volatile("mma.sync.aligned.m16n8k16.row.col.f32.f16.f16.f32 " \
        "{%0,%1,%2,%3}, {%4,%5,%6,%7}, {%8,%9}, {%0,%1,%2,%3};" \
        : "+f"((d)[0]), "+f"((d)[1]), "+f"((d)[2]), "+f"((d)[3]) \
        : "r"(a0), "r"(a1), "r"(a2), "r"(a3), "r"(b0), "r"(b1))

#define QMERGE(m1, c1, m2, XOR) do {                                  \
    float _o1 = __shfl_xor_sync(0xffffffffu, m1, XOR);                \
    int   _oc = __shfl_xor_sync(0xffffffffu, c1, XOR);                \
    float _o2 = __shfl_xor_sync(0xffffffffu, m2, XOR);                \
    bool _bet = (_o1 < m1) || (_o1 == m1 && _oc < c1);                \
    float _n2 = fminf(fminf(m2, _o2), _bet ? m1 : _o1);               \
    if (_bet) { m1 = _o1; c1 = _oc; }                                 \
    m2 = _n2; } while (0)

// prefetch one B chunk (128 codewords) into padded half tile
__device__ __forceinline__ void pf_chunk(char* dst, const __half* srcHi, int tid) {
#pragma unroll
    for (int jj = 0; jj < 4; ++jj) {
        int u = tid + 256*jj;
        int row = u >> 3, seg = u & 7;
        cp16(dst + row*(RSH*2) + seg*16, srcHi + (size_t)row*64 + seg*8);
    }
}

// ---------------- setup ------------------------------------------------------
__global__ void setup_kernel(const float* __restrict__ cb) {
    int gid = blockIdx.x * 256 + threadIdx.x;
    if (gid < K_*C_) g_counts[gid] = 0;
    int grp = threadIdx.x >> 6, ch = threadIdx.x & 63;
    int r = blockIdx.x * 4 + grp;             // 0..8191 = k*1024+c
    int k = r >> 10, c = r & 1023;
    float v = cb[(size_t)r * 64 + ch];
    g_cbHh[(size_t)r * 64 + ch] = __float2half_rn(v);
    g_cbT[((size_t)(k*64 + ch) << 10) + c] = v;
    if (ch == 0) {                            // exact cnorm, ref order
        const float* rp = cb + (size_t)r * 64;
        float s = 0.f;
        for (int d = 0; d < 64; ++d) s = fmaf(rp[d], rp[d], s);
        g_cnorm[r] = s;
    }
}

// ---------------- mega kernel ------------------------------------------------
__global__ __launch_bounds__(256, 3)
void vq_kernel(const float* __restrict__ x, const float* __restrict__ cb,
               float* __restrict__ out) {
    extern __shared__ __align__(16) char smem[];
    int*   sWin  = (int*)(smem + BWIN);
    int*   sList = (int*)(smem + BLIST);
    int*   sCnt  = (int*)(smem + BCNT);
    float* sCn   = (float*)(smem + BCN);
    float* sXn   = (float*)(smem + BXN);
    float* sRed  = (float*)(smem + BRED);

    const int tid = threadIdx.x, w = tid >> 5, lane = tid & 31;
    const int g = lane >> 2, tg = lane & 3, tg2 = tg * 2;
    const int b = blockIdx.z, k = blockIdx.y, t0 = blockIdx.x * TT;
    const int trow = w * 16;

    const __half* cbh = g_cbHh + ((size_t)k << 16);

    pf_chunk(smem + BBUF, cbh, tid);
    CP_COMMIT();

    // A build (fp16) + exact xn; cn copy
    if (tid == 0) *sCnt = 0;
    if (tid < 128) {
        const float* xb = x + ((size_t)(b*D_ + k*CH_)) * T_ + t0 + tid;
        __half* arh = (__half*)(smem + ABH) + tid * RSH;
        float xn = 0.f;
#pragma unroll
        for (int ch = 0; ch < 64; ++ch) {
            float v = xb[(size_t)ch * T_];
            xn = fmaf(v, v, xn);               // sequential (proven order)
            arh[ch] = __float2half_rn(v);
        }
        sXn[tid] = xn;
    } else {
        for (int i = tid - 128; i < 1024; i += 128)
            sCn[i] = g_cnorm[k*C_ + i];
    }
    __syncthreads();

    const float xnl = sXn[trow + g];
    const float xnh = sXn[trow + 8 + g];
    float gm1l = 3.4e38f, gm2l = 3.4e38f, gm1h = 3.4e38f, gm2h = 3.4e38f;
    int   gc1l = 0, gc1h = 0;

    // hoist A fragments once (chunk-invariant): 16 regs
    const uint32_t* a32h = (const uint32_t*)(smem + ABH);
    uint32_t af[16];
#pragma unroll
    for (int k0 = 0; k0 < 4; ++k0) {
        const int aw = (trow + g)*(RSH/2) + tg + 8*k0;
        af[k0*4+0] = a32h[aw];     af[k0*4+1] = a32h[aw + 8*(RSH/2)];
        af[k0*4+2] = a32h[aw + 4]; af[k0*4+3] = a32h[aw + 8*(RSH/2) + 4];
    }

#pragma unroll 1
    for (int i = 0; i < 8; ++i) {
        const int j = i & 1;
        if (i < 7) {
            pf_chunk(smem + BBUF + (j^1)*18432, cbh + (size_t)(i+1)*128*64, tid);
            CP_COMMIT();
            CP_WAIT1();
        } else CP_WAIT0();
        __syncthreads();

        const uint32_t* b32h = (const uint32_t*)(smem + BBUF + j*18432);

        // nt-outer / k0-inner: only acc[4] live; eval interleaves with MMA
#pragma unroll
        for (int nt = 0; nt < 16; ++nt) {
            float acc[4] = {0.f, 0.f, 0.f, 0.f};
#pragma unroll
            for (int k0 = 0; k0 < 4; ++k0) {
                const int bw = (nt*8 + g)*(RSH/2) + tg + 8*k0;
                MMA_F16(acc, af[k0*4+0], af[k0*4+1], af[k0*4+2], af[k0*4+3],
                        b32h[bw], b32h[bw + 4]);
            }
            const int c0 = i*128 + nt*8 + tg2;
            const float cn0 = sCn[c0], cn1 = sCn[c0 + 1];
            float d;
            d = fadd_rn(fadd_rn(xnl, cn0), -2.f*acc[0]);
            if (d < gm1l) { gm2l = gm1l; gm1l = d; gc1l = c0; } else if (d < gm2l) gm2l = d;
            d = fadd_rn(fadd_rn(xnl, cn1), -2.f*acc[1]);
            if (d < gm1l) { gm2l = gm1l; gm1l = d; gc1l = c0+1; } else if (d < gm2l) gm2l = d;
            d = fadd_rn(fadd_rn(xnh, cn0), -2.f*acc[2]);
            if (d < gm1h) { gm2h = gm1h; gm1h = d; gc1h = c0; } else if (d < gm2h) gm2h = d;
            d = fadd_rn(fadd_rn(xnh, cn1), -2.f*acc[3]);
            if (d < gm1h) { gm2h = gm1h; gm1h = d; gc1h = c0+1; } else if (d < gm2h) gm2h = d;
        }
        __syncthreads();
    }

    QMERGE(gm1l, gc1l, gm2l, 1); QMERGE(gm1l, gc1l, gm2l, 2);
    QMERGE(gm1h, gc1h, gm2h, 1); QMERGE(gm1h, gc1h, gm2h, 2);
    if (tg == 0) {
        int tl = trow + g, th = trow + 8 + g;
        sWin[tl] = gc1l; sWin[th] = gc1h;
        if (gm2l - gm1l < EPS) { int p = atomicAdd(sCnt, 1); sList[p] = tl; }
        if (gm2h - gm1h < EPS) { int p = atomicAdd(sCnt, 1); sList[p] = th; }
    }
    __syncthreads();

    // ---- warp-parallel exact rescue (bit-proven R2 comparator) ----
    const int nR = *sCnt;
    for (int base = 0; base < nR; base += 8) {
        int li = base + w;
        if (li < nR) {
            int tt = sList[li];
            float* xr = (float*)(smem + BXROW) + w*64;
            xr[lane]      = x[((size_t)(b*D_ + k*CH_ + lane))      * T_ + t0 + tt];
            xr[lane + 32] = x[((size_t)(b*D_ + k*CH_ + lane + 32)) * T_ + t0 + tt];
            __syncwarp();
            float dots[32];
#pragma unroll
            for (int q = 0; q < 32; ++q) dots[q] = 0.f;
            const float* cpk = g_cbT + ((size_t)(k*CH_) << 10) + lane;
#pragma unroll 4
            for (int ch = 0; ch < 64; ++ch) {
                float xv = xr[ch];
                const float* pr = cpk + ((size_t)ch << 10);
#pragma unroll
                for (int q = 0; q < 32; ++q)
                    dots[q] = fmaf(xv, pr[q*32], dots[q]);
            }
            float xnt = sXn[tt];
            float bv = 3.4e38f; int bc = 0;
#pragma unroll
            for (int q = 0; q < 32; ++q) {
                int c = lane + 32*q;
                float d = fadd_rn(fadd_rn(xnt, g_cnorm[k*C_ + c]), -2.f*dots[q]);
                if (d < bv) { bv = d; bc = c; }
            }
#pragma unroll
            for (int off = 16; off; off >>= 1) {
                float ov = __shfl_xor_sync(0xffffffffu, bv, off);
                int   oc = __shfl_xor_sync(0xffffffffu, bc, off);
                if (ov < bv || (ov == bv && oc < bc)) { bv = ov; bc = oc; }
            }
            if (lane == 0) sWin[tt] = bc;
        }
    }
    __syncthreads();

    if (tid < 128) atomicAdd(&g_counts[k*C_ + sWin[tid]], 1);

    // ---- epilogue: gather q, write quantized, MSE partial ----
    float* sQ = (float*)(smem + BBUF);
    float lacc = 0.f;
    if (tid < 128) {
        const int myc = sWin[tid];
        const float4* qrow = (const float4*)(cb + ((size_t)(k*C_ + myc)) * CH_);
        float4 qv4[16];
#pragma unroll
        for (int i = 0; i < 16; ++i) qv4[i] = qrow[i];
        const float* qf = (const float*)qv4;
        const __half* arh = (const __half*)(smem + ABH) + tid * RSH;
#pragma unroll
        for (int ch = 0; ch < 64; ++ch) {
            float qv = qf[ch];
            sQ[ch*TT + tid] = qv;
            float dd = __half2float(arh[ch]) - qv;   // x@fp16: loss err ~1e-7 rel
            lacc = fmaf(dd, dd, lacc);
        }
    }
    __syncthreads();
    {
        float* ob = out + ((size_t)(b*D_ + k*CH_)) * T_ + t0;
#pragma unroll
        for (int jj = 0; jj < 8; ++jj) {
            int u = tid + 256*jj;
            int ch = u >> 5, c4 = (u & 31) << 2;
            float4 v = *reinterpret_cast<const float4*>(&sQ[ch*TT + c4]);
            *reinterpret_cast<float4*>(ob + (size_t)ch * T_ + c4) = v;
        }
    }
    sRed[tid] = lacc;
    __syncthreads();
    for (int s = 128; s > 0; s >>= 1) {
        if (tid < s) sRed[tid] += sRed[tid + s];
        __syncthreads();
    }
    if (tid == 0)
        g_loss_partial[(b*K_ + k)*(T_/TT) + blockIdx.x] = sRed[0];
}

// ---------------- finalize: 9 blocks (8 perplexity + 1 loss) -----------------
__global__ void finalize_kernel(float* __restrict__ out) {
    const int tid = threadIdx.x;
    const int kb = blockIdx.x;
    __shared__ float sred[256];

    if (kb == 8) {
        float s = 0.f;
#pragma unroll
        for (int j = 0; j < NBLK/256; ++j) s += g_loss_partial[tid + 256*j];
        sred[tid] = s;
        __syncthreads();
#pragma unroll
        for (int st = 128; st > 0; st >>= 1) {
            if (tid < st) sred[tid] += sred[tid + st];
            __syncthreads();
        }
        if (tid == 0) out[NQ] = sred[0] * 1.25f / (float)NQ;
    } else {
        float h = 0.f;
#pragma unroll
        for (int j = 0; j < 4; ++j) {
            float p = (float)g_counts[kb*C_ + tid + 256*j] * (1.f / (B_*T_));
            h += -p * logf(p + 1e-8f);
        }
        sred[tid] = h;
        __syncthreads();
#pragma unroll
        for (int st = 128; st > 0; st >>= 1) {
            if (tid < st) sred[tid] += sred[tid + st];
            __syncthreads();
        }
        if (tid == 0) out[NQ + 1 + kb] = expf(sred[0]);
    }
}

// ---------------- launch -----------------------------------------------------
extern "C" void kernel_launch(void* const* d_in, const int* in_sizes, int n_in,
                              void* d_out, int out_size) {
    const float* x  = (const float*)d_in[0];
    const float* cb = (const float*)d_in[1];
    float* out = (float*)d_out;

    cudaFuncSetAttribute(vq_kernel,
                         cudaFuncAttributeMaxDynamicSharedMemorySize, SMEM_BYTES);

    setup_kernel<<<2048, 256>>>(cb);
    vq_kernel<<<dim3(T_/TT, K_, B_), 256, SMEM_BYTES>>>(x, cb, out);
    finalize_kernel<<<9, 256>>>(out);
}

// round 17
// speedup vs baseline: 1.5457x; 1.5457x over previous
#include <cuda_runtime.h>
#include <cuda_fp16.h>
#include <math.h>
#include <stdint.h>

#define B_  16
#define D_  512
#define T_  2048
#define K_  8
#define C_  1024
#define CH_ 64
#define NQ  (B_*D_*T_)
#define TT  128
#define NBLK 2048
#define EPS 1e-2f
#define RSH 72                  // padded half row stride

// smem byte offsets
#define ABH   0                 // A: 128 x 72 halfs = 18432 B
#define BBUF  18432             // 2 bufs x 18432
#define BCN   55296             // float[1024]
#define BXN   59392             // float[128]
#define BWIN  59904             // int[128]
#define BLIST 60416             // int[128]
#define BCNT  60928             // int (pad 16)
#define BRED  60944             // float[256]
#define BXROW 61968             // float[8*64]
#define SMEM_BYTES 64016

// ---------------- scratch ----------------------------------------------------
__device__ int    g_counts[K_*C_];
__device__ float  g_cnorm[K_*C_];
__device__ float  g_cbT[K_*CH_*C_];     // exact, [k][ch][c] (rescue path)
__device__ __half g_cbHh[K_*C_*CH_];    // fp16, [k][c][ch]
__device__ float  g_loss_partial[NBLK];

// ---------------- helpers ----------------------------------------------------
__device__ __forceinline__ float fadd_rn(float a, float b) {
    float r; asm("add.f32 %0, %1, %2;" : "=f"(r) : "f"(a), "f"(b)); return r;
}
__device__ __forceinline__ void cp16(void* smem_dst, const void* gmem_src) {
    unsigned s = (unsigned)__cvta_generic_to_shared(smem_dst);
    asm volatile("cp.async.cg.shared.global [%0], [%1], 16;" :: "r"(s), "l"(gmem_src) : "memory");
}
#define CP_COMMIT() asm volatile("cp.async.commit_group;" ::: "memory")
#define CP_WAIT0()  asm volatile("cp.async.wait_group 0;" ::: "memory")

#define MMA_F16(d, a0,a1,a2,a3, b0,b1) \
    asm volatile("mma.sync.aligned.m16n8k16.row.col.f32.f16.f16.f32 " \
        "{%0,%1,%2,%3}, {%4,%5,%6,%7}, {%8,%9}, {%0,%1,%2,%3};" \
        : "+f"((d)[0]), "+f"((d)[1]), "+f"((d)[2]), "+f"((d)[3]) \
        : "r"(a0), "r"(a1), "r"(a2), "r"(a3), "r"(b0), "r"(b1))

#define QMERGE(m1, c1, m2, XOR) do {                                  \
    float _o1 = __shfl_xor_sync(0xffffffffu, m1, XOR);                \
    int   _oc = __shfl_xor_sync(0xffffffffu, c1, XOR);                \
    float _o2 = __shfl_xor_sync(0xffffffffu, m2, XOR);                \
    bool _bet = (_o1 < m1) || (_o1 == m1 && _oc < c1);                \
    float _n2 = fminf(fminf(m2, _o2), _bet ? m1 : _o1);               \
    if (_bet) { m1 = _o1; c1 = _oc; }                                 \
    m2 = _n2; } while (0)

// prefetch one B chunk (128 codewords) into padded half tile
__device__ __forceinline__ void pf_chunk(char* dst, const __half* srcHi, int tid) {
#pragma unroll
    for (int jj = 0; jj < 4; ++jj) {
        int u = tid + 256*jj;
        int row = u >> 3, seg = u & 7;
        cp16(dst + row*(RSH*2) + seg*16, srcHi + (size_t)row*64 + seg*8);
    }
}

// ---------------- setup ------------------------------------------------------
__global__ void setup_kernel(const float* __restrict__ cb) {
    int gid = blockIdx.x * 256 + threadIdx.x;
    if (gid < K_*C_) g_counts[gid] = 0;
    int grp = threadIdx.x >> 6, ch = threadIdx.x & 63;
    int r = blockIdx.x * 4 + grp;             // 0..8191 = k*1024+c
    int k = r >> 10, c = r & 1023;
    float v = cb[(size_t)r * 64 + ch];
    g_cbHh[(size_t)r * 64 + ch] = __float2half_rn(v);
    g_cbT[((size_t)(k*64 + ch) << 10) + c] = v;
    if (ch == 0) {                            // exact cnorm, ref order
        const float* rp = cb + (size_t)r * 64;
        float s = 0.f;
        for (int d = 0; d < 64; ++d) s = fmaf(rp[d], rp[d], s);
        g_cnorm[r] = s;
    }
}

// ---------------- mega kernel ------------------------------------------------
__global__ __launch_bounds__(256, 2)
void vq_kernel(const float* __restrict__ x, const float* __restrict__ cb,
               float* __restrict__ out) {
    extern __shared__ __align__(16) char smem[];
    int*   sWin  = (int*)(smem + BWIN);
    int*   sList = (int*)(smem + BLIST);
    int*   sCnt  = (int*)(smem + BCNT);
    float* sCn   = (float*)(smem + BCN);
    float* sXn   = (float*)(smem + BXN);
    float* sRed  = (float*)(smem + BRED);

    const int tid = threadIdx.x, w = tid >> 5, lane = tid & 31;
    const int g = lane >> 2, tg = lane & 3, tg2 = tg * 2;
    const int b = blockIdx.z, k = blockIdx.y, t0 = blockIdx.x * TT;
    const int trow = w * 16;

    const __half* cbh = g_cbHh + ((size_t)k << 16);

    pf_chunk(smem + BBUF, cbh, tid);
    CP_COMMIT();

    // A build (fp16) + exact xn; cn copy
    if (tid == 0) *sCnt = 0;
    if (tid < 128) {
        const float* xb = x + ((size_t)(b*D_ + k*CH_)) * T_ + t0 + tid;
        __half* arh = (__half*)(smem + ABH) + tid * RSH;
        float xn = 0.f;
#pragma unroll
        for (int ch = 0; ch < 64; ++ch) {
            float v = xb[(size_t)ch * T_];
            xn = fmaf(v, v, xn);               // sequential (proven order)
            arh[ch] = __float2half_rn(v);
        }
        sXn[tid] = xn;
    } else {
        for (int i = tid - 128; i < 1024; i += 128)
            sCn[i] = g_cnorm[k*C_ + i];
    }
    __syncthreads();                           // A + cn ready

    const float xnl = sXn[trow + g];
    const float xnh = sXn[trow + 8 + g];
    float gm1l = 3.4e38f, gm2l = 3.4e38f, gm1h = 3.4e38f, gm2h = 3.4e38f;
    int   gc1l = 0, gc1h = 0;

    // hoist A fragments once (chunk-invariant): 16 regs
    const uint32_t* a32h = (const uint32_t*)(smem + ABH);
    uint32_t af[16];
#pragma unroll
    for (int k0 = 0; k0 < 4; ++k0) {
        const int aw = (trow + g)*(RSH/2) + tg + 8*k0;
        af[k0*4+0] = a32h[aw];     af[k0*4+1] = a32h[aw + 8*(RSH/2)];
        af[k0*4+2] = a32h[aw + 4]; af[k0*4+3] = a32h[aw + 8*(RSH/2) + 4];
    }

#pragma unroll 1
    for (int i = 0; i < 8; ++i) {
        const int j = i & 1;
        CP_WAIT0();
        __syncthreads();      // chunk i ready AND all warps done with buf j (iter i-1... i-2)
        if (i < 7) {
            // safe: every warp passing the sync has finished reading buf j^1 (iter i-1)
            pf_chunk(smem + BBUF + (j^1)*18432, cbh + (size_t)(i+1)*128*64, tid);
            CP_COMMIT();
        }

        const uint32_t* b32h = (const uint32_t*)(smem + BBUF + j*18432);
        float acc[64];
#pragma unroll
        for (int q = 0; q < 64; ++q) acc[q] = 0.f;

        // k0-outer / nt-inner: 16 independent MMA chains (R11 proven structure)
#pragma unroll
        for (int k0 = 0; k0 < 4; ++k0) {
#pragma unroll
            for (int nt = 0; nt < 16; ++nt) {
                const int bw = (nt*8 + g)*(RSH/2) + tg + 8*k0;
                MMA_F16(acc + nt*4, af[k0*4+0], af[k0*4+1], af[k0*4+2], af[k0*4+3],
                        b32h[bw], b32h[bw + 4]);
            }
        }
        // eval: reference-exact rounding (fl(fl(xn+cn)+(-2*dot)))
#pragma unroll
        for (int nt = 0; nt < 16; ++nt) {
            const int c0 = i*128 + nt*8 + tg2;
            const float cn0 = sCn[c0], cn1 = sCn[c0 + 1];
            float d;
            d = fadd_rn(fadd_rn(xnl, cn0), -2.f*acc[nt*4+0]);
            if (d < gm1l) { gm2l = gm1l; gm1l = d; gc1l = c0; } else if (d < gm2l) gm2l = d;
            d = fadd_rn(fadd_rn(xnl, cn1), -2.f*acc[nt*4+1]);
            if (d < gm1l) { gm2l = gm1l; gm1l = d; gc1l = c0+1; } else if (d < gm2l) gm2l = d;
            d = fadd_rn(fadd_rn(xnh, cn0), -2.f*acc[nt*4+2]);
            if (d < gm1h) { gm2h = gm1h; gm1h = d; gc1h = c0; } else if (d < gm2h) gm2h = d;
            d = fadd_rn(fadd_rn(xnh, cn1), -2.f*acc[nt*4+3]);
            if (d < gm1h) { gm2h = gm1h; gm1h = d; gc1h = c0+1; } else if (d < gm2h) gm2h = d;
        }
    }
    __syncthreads();   // last chunk reads done before smem reuse below

    QMERGE(gm1l, gc1l, gm2l, 1); QMERGE(gm1l, gc1l, gm2l, 2);
    QMERGE(gm1h, gc1h, gm2h, 1); QMERGE(gm1h, gc1h, gm2h, 2);
    if (tg == 0) {
        int tl = trow + g, th = trow + 8 + g;
        sWin[tl] = gc1l; sWin[th] = gc1h;
        if (gm2l - gm1l < EPS) { int p = atomicAdd(sCnt, 1); sList[p] = tl; }
        if (gm2h - gm1h < EPS) { int p = atomicAdd(sCnt, 1); sList[p] = th; }
    }
    __syncthreads();

    // ---- warp-parallel exact rescue (bit-proven R2 comparator) ----
    const int nR = *sCnt;
    for (int base = 0; base < nR; base += 8) {
        int li = base + w;
        if (li < nR) {
            int tt = sList[li];
            float* xr = (float*)(smem + BXROW) + w*64;
            xr[lane]      = x[((size_t)(b*D_ + k*CH_ + lane))      * T_ + t0 + tt];
            xr[lane + 32] = x[((size_t)(b*D_ + k*CH_ + lane + 32)) * T_ + t0 + tt];
            __syncwarp();
            float dots[32];
#pragma unroll
            for (int q = 0; q < 32; ++q) dots[q] = 0.f;
            const float* cpk = g_cbT + ((size_t)(k*CH_) << 10) + lane;
#pragma unroll 4
            for (int ch = 0; ch < 64; ++ch) {
                float xv = xr[ch];
                const float* pr = cpk + ((size_t)ch << 10);
#pragma unroll
                for (int q = 0; q < 32; ++q)
                    dots[q] = fmaf(xv, pr[q*32], dots[q]);
            }
            float xnt = sXn[tt];
            float bv = 3.4e38f; int bc = 0;
#pragma unroll
            for (int q = 0; q < 32; ++q) {
                int c = lane + 32*q;
                float d = fadd_rn(fadd_rn(xnt, g_cnorm[k*C_ + c]), -2.f*dots[q]);
                if (d < bv) { bv = d; bc = c; }
            }
#pragma unroll
            for (int off = 16; off; off >>= 1) {
                float ov = __shfl_xor_sync(0xffffffffu, bv, off);
                int   oc = __shfl_xor_sync(0xffffffffu, bc, off);
                if (ov < bv || (ov == bv && oc < bc)) { bv = ov; bc = oc; }
            }
            if (lane == 0) sWin[tt] = bc;
        }
    }
    __syncthreads();

    if (tid < 128) atomicAdd(&g_counts[k*C_ + sWin[tid]], 1);

    // ---- epilogue: gather q, write quantized, MSE partial ----
    float* sQ = (float*)(smem + BBUF);
    float lacc = 0.f;
    if (tid < 128) {
        const int myc = sWin[tid];
        const float4* qrow = (const float4*)(cb + ((size_t)(k*C_ + myc)) * CH_);
        float4 qv4[16];
#pragma unroll
        for (int i = 0; i < 16; ++i) qv4[i] = qrow[i];
        const float* qf = (const float*)qv4;
        const __half* arh = (const __half*)(smem + ABH) + tid * RSH;
#pragma unroll
        for (int ch = 0; ch < 64; ++ch) {
            float qv = qf[ch];
            sQ[ch*TT + tid] = qv;
            float dd = __half2float(arh[ch]) - qv;   // x@fp16: loss err ~1e-7 rel
            lacc = fmaf(dd, dd, lacc);
        }
    }
    __syncthreads();
    {
        float* ob = out + ((size_t)(b*D_ + k*CH_)) * T_ + t0;
#pragma unroll
        for (int jj = 0; jj < 8; ++jj) {
            int u = tid + 256*jj;
            int ch = u >> 5, c4 = (u & 31) << 2;
            float4 v = *reinterpret_cast<const float4*>(&sQ[ch*TT + c4]);
            *reinterpret_cast<float4*>(ob + (size_t)ch * T_ + c4) = v;
        }
    }
    sRed[tid] = lacc;
    __syncthreads();
    for (int s = 128; s > 0; s >>= 1) {
        if (tid < s) sRed[tid] += sRed[tid + s];
        __syncthreads();
    }
    if (tid == 0)
        g_loss_partial[(b*K_ + k)*(T_/TT) + blockIdx.x] = sRed[0];
}

// ---------------- finalize: 9 blocks (8 perplexity + 1 loss) -----------------
__global__ void finalize_kernel(float* __restrict__ out) {
    const int tid = threadIdx.x;
    const int kb = blockIdx.x;
    __shared__ float sred[256];

    if (kb == 8) {
        float s = 0.f;
#pragma unroll
        for (int j = 0; j < NBLK/256; ++j) s += g_loss_partial[tid + 256*j];
        sred[tid] = s;
        __syncthreads();
#pragma unroll
        for (int st = 128; st > 0; st >>= 1) {
            if (tid < st) sred[tid] += sred[tid + st];
            __syncthreads();
        }
        if (tid == 0) out[NQ] = sred[0] * 1.25f / (float)NQ;
    } else {
        float h = 0.f;
#pragma unroll
        for (int j = 0; j < 4; ++j) {
            float p = (float)g_counts[kb*C_ + tid + 256*j] * (1.f / (B_*T_));
            h += -p * logf(p + 1e-8f);
        }
        sred[tid] = h;
        __syncthreads();
#pragma unroll
        for (int st = 128; st > 0; st >>= 1) {
            if (tid < st) sred[tid] += sred[tid + st];
            __syncthreads();
        }
        if (tid == 0) out[NQ + 1 + kb] = expf(sred[0]);
    }
}

// ---------------- launch -----------------------------------------------------
extern "C" void kernel_launch(void* const* d_in, const int* in_sizes, int n_in,
                              void* d_out, int out_size) {
    const float* x  = (const float*)d_in[0];
    const float* cb = (const float*)d_in[1];
    float* out = (float*)d_out;

    cudaFuncSetAttribute(vq_kernel,
                         cudaFuncAttributeMaxDynamicSharedMemorySize, SMEM_BYTES);

    setup_kernel<<<2048, 256>>>(cb);
    vq_kernel<<<dim3(T_/TT, K_, B_), 256, SMEM_BYTES>>>(x, cb, out);
    finalize_kernel<<<9, 256>>>(out);
}